// round 1
// baseline (speedup 1.0000x reference)
#include <cuda_runtime.h>

#define NB    32
#define C_IN  64
#define HH    64
#define WWW   64
#define C_OUT 128
#define CONN  4
#define ROWS  16   // ho rows per block

__global__ __launch_bounds__(256) void lp_conv_bt_kernel(
    const float* __restrict__ x,      // (32,64,64,64)
    const float* __restrict__ w,      // (128,4)
    const float* __restrict__ bias,   // (128)
    const int*   __restrict__ conn,   // (128,4)
    float*       __restrict__ out)    // (32,128,64,64)
{
    const int qx  = threadIdx.x;                 // 0..15 -> wo quad
    const int ho  = blockIdx.x * ROWS + threadIdx.y;
    const int b   = blockIdx.y;
    const int co  = blockIdx.z;
    const int wo0 = qx * 4;

    float a0 = 0.f, a1 = 0.f, a2 = 0.f, a3 = 0.f;  // |.| >= 0 so 0 is a safe identity

    #pragma unroll
    for (int j = 0; j < CONN; ++j) {
        const int   idx = __ldg(&conn[co * CONN + j]);
        const float wj  = __ldg(&w[co * CONN + j]);

        const int c   = idx / 9;
        const int rem = idx - c * 9;
        const int di  = rem / 3;
        const int dj  = rem - di * 3;

        // edge padding: pad_l = pad_r = 1 -> clamp source coords into [0,63]
        const int sh = min(max(ho + di - 1, 0), HH - 1);
        const float* __restrict__ row = x + (((b * C_IN + c) * HH + sh) * WWW);

        const int base = wo0 + dj - 1;
        const float v0 = __ldg(&row[min(max(base + 0, 0), WWW - 1)]);
        const float v1 = __ldg(&row[min(max(base + 1, 0), WWW - 1)]);
        const float v2 = __ldg(&row[min(max(base + 2, 0), WWW - 1)]);
        const float v3 = __ldg(&row[min(max(base + 3, 0), WWW - 1)]);

        a0 = fmaxf(a0, fabsf(wj - v0));
        a1 = fmaxf(a1, fabsf(wj - v1));
        a2 = fmaxf(a2, fabsf(wj - v2));
        a3 = fmaxf(a3, fabsf(wj - v3));
    }

    const float bs = __ldg(&bias[co]);
    float4 r;
    r.x = a0 + bs; r.y = a1 + bs; r.z = a2 + bs; r.w = a3 + bs;

    const long long obase = (((long long)(b * C_OUT + co) * HH + ho) * WWW + wo0);
    *reinterpret_cast<float4*>(out + obase) = r;
}

extern "C" void kernel_launch(void* const* d_in, const int* in_sizes, int n_in,
                              void* d_out, int out_size)
{
    const float* x    = (const float*)d_in[0];
    const float* w    = (const float*)d_in[1];
    const float* bias = (const float*)d_in[2];
    const int*   conn = (const int*)  d_in[3];
    float*       out  = (float*)d_out;

    dim3 block(16, ROWS);                 // 256 threads, 64 wo x 16 ho
    dim3 grid(HH / ROWS, NB, C_OUT);      // (4, 32, 128)
    lp_conv_bt_kernel<<<grid, block>>>(x, w, bias, conn, out);
}